// round 2
// baseline (speedup 1.0000x reference)
#include <cuda_runtime.h>
#include <math.h>

#define NN 8192
#define DD 256
#define TK 5
#define TOPC 8   // candidates kept per row before exact A-level selection

// ---------------- device scratch (no allocations allowed) ----------------
__device__ float g_psum[32][DD];
__device__ float g_psq[32][DD];
__device__ float g_scale[DD];
__device__ float g_shift[DD];
__device__ float g_HnT[DD * NN];   // transposed normalized input [k][row]
__device__ float g_Hx[NN * DD];    // theta projection (row-major, pre-normalize)
__device__ float g_F1T[DD * NN];   // normalized F1, transposed [k][row]
__device__ float g_G[NN * DD];     // Hn @ W_out + b_out (row-major)
__device__ float g_tv[NN * TK];    // top-5 A values per row
__device__ int   g_ti[NN * TK];    // top-5 indices per row
__device__ float g_dinv[NN];

// ---------------- 1) batchnorm stats: partial sums ----------------
__global__ void k_stats1(const float* __restrict__ H) {
    int b = blockIdx.x, t = threadIdx.x;
    const float* p = H + (size_t)b * 256 * DD + t;
    float s = 0.f, q = 0.f;
#pragma unroll 8
    for (int r = 0; r < 256; r++) {
        float x = p[(size_t)r * DD];
        s += x; q += x * x;
    }
    g_psum[b][t] = s;
    g_psq[b][t]  = q;
}

// ---------------- 2) finalize stats ----------------
__global__ void k_stats2(const float* __restrict__ gamma, const float* __restrict__ beta) {
    int t = threadIdx.x;
    float s = 0.f, q = 0.f;
    for (int b = 0; b < 32; b++) { s += g_psum[b][t]; q += g_psq[b][t]; }
    float mu  = s * (1.f / NN);
    float var = q * (1.f / NN) - mu * mu;
    float sc  = gamma[t] * rsqrtf(var + 1e-5f);
    g_scale[t] = sc;
    g_shift[t] = beta[t] - mu * sc;
}

// ---------------- 3) Hn (normalized), written TRANSPOSED [k][row] ----------------
__global__ void k_hnT(const float* __restrict__ H) {
    __shared__ float buf[32 * 257];
    int r0 = blockIdx.x * 32;
    int tid = threadIdx.x;
#pragma unroll
    for (int it = 0; it < 8; it++) {
        int e = it * 256 + tid;        // float4 index within 32x64 float4s
        int r = e >> 6;
        int c = (e & 63) * 4;
        float4 h = *(const float4*)(H + (size_t)(r0 + r) * DD + c);
        buf[r * 257 + c + 0] = fmaf(h.x, g_scale[c + 0], g_shift[c + 0]);
        buf[r * 257 + c + 1] = fmaf(h.y, g_scale[c + 1], g_shift[c + 1]);
        buf[r * 257 + c + 2] = fmaf(h.z, g_scale[c + 2], g_shift[c + 2]);
        buf[r * 257 + c + 3] = fmaf(h.w, g_scale[c + 3], g_shift[c + 3]);
    }
    __syncthreads();
    int lane = tid & 31;
    int cbase = tid >> 5;
#pragma unroll
    for (int it = 0; it < 32; it++) {
        int c = cbase + it * 8;
        g_HnT[(size_t)c * NN + r0 + lane] = buf[lane * 257 + c];
    }
}

// ---------------- 4) GEMM: [Hx | G] = Hn @ [W_theta | W_out] + bias ----------------
__global__ __launch_bounds__(256) void k_gemm(
    const float* __restrict__ Wt, const float* __restrict__ bt,
    const float* __restrict__ Wo, const float* __restrict__ bo) {
    __shared__ float As[64 * 64];  // [k][r]
    __shared__ float Bs[64 * 64];  // [k][n]
    int tid = threadIdx.x, tx = tid & 15, ty = tid >> 4;
    int i0 = blockIdx.x * 64;
    int by = blockIdx.y;
    const float* W    = (by < 4) ? Wt : Wo;
    const float* bias = (by < 4) ? bt : bo;
    float* C          = (by < 4) ? g_Hx : g_G;
    int n0 = (by & 3) * 64;

    float acc[4][4] = {};
    for (int kc = 0; kc < 256; kc += 64) {
#pragma unroll
        for (int it = 0; it < 4; it++) {
            int e = it * 256 + tid;
            int k = e >> 4, r4 = e & 15;
            float4 v = *(const float4*)(g_HnT + (size_t)(kc + k) * NN + i0 + r4 * 4);
            *(float4*)(As + k * 64 + r4 * 4) = v;
        }
#pragma unroll
        for (int it = 0; it < 4; it++) {
            int e = it * 256 + tid;
            int k = e >> 4, n4 = e & 15;
            float4 v = *(const float4*)(W + (size_t)(kc + k) * DD + n0 + n4 * 4);
            *(float4*)(Bs + k * 64 + n4 * 4) = v;
        }
        __syncthreads();
#pragma unroll 8
        for (int k = 0; k < 64; k++) {
            float4 a = *(const float4*)(As + k * 64 + ty * 4);
            float4 b = *(const float4*)(Bs + k * 64 + tx * 4);
            acc[0][0] += a.x * b.x; acc[0][1] += a.x * b.y; acc[0][2] += a.x * b.z; acc[0][3] += a.x * b.w;
            acc[1][0] += a.y * b.x; acc[1][1] += a.y * b.y; acc[1][2] += a.y * b.z; acc[1][3] += a.y * b.w;
            acc[2][0] += a.z * b.x; acc[2][1] += a.z * b.y; acc[2][2] += a.z * b.z; acc[2][3] += a.z * b.w;
            acc[3][0] += a.w * b.x; acc[3][1] += a.w * b.y; acc[3][2] += a.w * b.z; acc[3][3] += a.w * b.w;
        }
        __syncthreads();
    }
#pragma unroll
    for (int q = 0; q < 4; q++) {
        int r = i0 + ty * 4 + q;
#pragma unroll
        for (int p = 0; p < 4; p++) {
            int n = n0 + tx * 4 + p;
            C[(size_t)r * DD + n] = acc[q][p] + bias[n];
        }
    }
}

// ---------------- 5) row-normalize Hx -> F1, written TRANSPOSED ----------------
__global__ void k_norm() {
    __shared__ float buf[32 * 257];
    int r0 = blockIdx.x * 32;
    int tid = threadIdx.x, w = tid >> 5, lane = tid & 31;
#pragma unroll
    for (int rr = w * 4; rr < w * 4 + 4; rr++) {
        const float* row = g_Hx + (size_t)(r0 + rr) * DD;
        float4 x0 = ((const float4*)row)[lane];
        float4 x1 = ((const float4*)row)[lane + 32];
        float s = x0.x * x0.x + x0.y * x0.y + x0.z * x0.z + x0.w * x0.w
                + x1.x * x1.x + x1.y * x1.y + x1.z * x1.z + x1.w * x1.w;
#pragma unroll
        for (int o = 16; o > 0; o >>= 1) s += __shfl_xor_sync(0xffffffffu, s, o);
        float inv = 1.f / fmaxf(sqrtf(s), 1e-12f);
        int c0 = lane * 4, c1 = 128 + lane * 4;
        buf[rr * 257 + c0 + 0] = x0.x * inv; buf[rr * 257 + c0 + 1] = x0.y * inv;
        buf[rr * 257 + c0 + 2] = x0.z * inv; buf[rr * 257 + c0 + 3] = x0.w * inv;
        buf[rr * 257 + c1 + 0] = x1.x * inv; buf[rr * 257 + c1 + 1] = x1.y * inv;
        buf[rr * 257 + c1 + 2] = x1.z * inv; buf[rr * 257 + c1 + 3] = x1.w * inv;
    }
    __syncthreads();
    int cbase = tid >> 5;
#pragma unroll
    for (int it = 0; it < 32; it++) {
        int c = cbase + it * 8;
        g_F1T[(size_t)c * NN + r0 + lane] = buf[lane * 257 + c];
    }
}

// map clipped cosine -> A value, matching the reference formula in fp32
__device__ __forceinline__ float affinity(float d) {
    d = fminf(fmaxf(d, -1.f), 1.f);
    float sam = acosf(d);
    float e = expf(-0.2f * sam);
    float a = 1.f / (1.f + expf(-e));
    return fmaxf(a, 0.1f);
}

// ---------------- 6) main: S = F1 F1^T fused with per-row top-k ----------------
__global__ __launch_bounds__(256) void k_main() {
    extern __shared__ float sm[];
    float* Fi = sm;                    // 256 x 64 [k][r]
    float* Fj = sm + 256 * 64;         // 256 x 64 [k][r]
    float* S  = sm + 2 * 256 * 64;     // 64 x 65 (padded)

    int tid = threadIdx.x, tx = tid & 15, ty = tid >> 4;
    int i0 = blockIdx.x * 64;

#pragma unroll
    for (int it = 0; it < 16; it++) {
        int e = it * 256 + tid;
        int k = e >> 4, r4 = e & 15;
        float4 v = *(const float4*)(g_F1T + (size_t)k * NN + i0 + r4 * 4);
        *(float4*)(Fi + k * 64 + r4 * 4) = v;
    }

    // per-row top-8 candidates by raw dot, index-ascending scan, strict-greater
    // insertion => lowest index kept among exact dot ties
    float dv[TOPC]; int dj[TOPC];
#pragma unroll
    for (int m = 0; m < TOPC; m++) { dv[m] = -2.f; dj[m] = 0; }

    for (int jt = 0; jt < NN / 64; jt++) {
        int j0 = jt * 64;
#pragma unroll
        for (int it = 0; it < 16; it++) {
            int e = it * 256 + tid;
            int k = e >> 4, r4 = e & 15;
            float4 v = *(const float4*)(g_F1T + (size_t)k * NN + j0 + r4 * 4);
            *(float4*)(Fj + k * 64 + r4 * 4) = v;
        }
        __syncthreads();

        float acc[4][4] = {};
#pragma unroll 4
        for (int k = 0; k < 256; k++) {
            float4 a = *(const float4*)(Fi + k * 64 + ty * 4);
            float4 b = *(const float4*)(Fj + k * 64 + tx * 4);
            acc[0][0] += a.x * b.x; acc[0][1] += a.x * b.y; acc[0][2] += a.x * b.z; acc[0][3] += a.x * b.w;
            acc[1][0] += a.y * b.x; acc[1][1] += a.y * b.y; acc[1][2] += a.y * b.z; acc[1][3] += a.y * b.w;
            acc[2][0] += a.z * b.x; acc[2][1] += a.z * b.y; acc[2][2] += a.z * b.z; acc[2][3] += a.z * b.w;
            acc[3][0] += a.w * b.x; acc[3][1] += a.w * b.y; acc[3][2] += a.w * b.z; acc[3][3] += a.w * b.w;
        }
        __syncthreads();
#pragma unroll
        for (int q = 0; q < 4; q++)
#pragma unroll
            for (int p = 0; p < 4; p++)
                S[(ty * 4 + q) * 65 + tx * 4 + p] = acc[q][p];
        __syncthreads();

        if (tid < 64) {
#pragma unroll 4
            for (int c = 0; c < 64; c++) {
                float v = S[tid * 65 + c];
                if (v > dv[TOPC - 1]) {
                    dv[TOPC - 1] = v; dj[TOPC - 1] = j0 + c;
                    // one bubble pass restores sortedness (only tail is new);
                    // equal values do NOT swap => earlier index stays in front
#pragma unroll
                    for (int m = TOPC - 1; m > 0; m--) {
                        if (dv[m] > dv[m - 1]) {
                            float t = dv[m]; dv[m] = dv[m - 1]; dv[m - 1] = t;
                            int u = dj[m]; dj[m] = dj[m - 1]; dj[m - 1] = u;
                        }
                    }
                }
            }
        }
        __syncthreads();
    }

    if (tid < 64) {
        int i = i0 + tid;
        // exact A values for the 8 candidates
        float av[TOPC];
#pragma unroll
        for (int m = 0; m < TOPC; m++) av[m] = affinity(dv[m]);

        // stable re-sort by (A desc, index asc) — resolves A-level ties the
        // same way lax.top_k does (lowest index first)
#pragma unroll
        for (int m = 1; m < TOPC; m++) {
#pragma unroll
            for (int p = TOPC - 1; p >= 1; p--) {
                bool sw = (av[p] > av[p - 1]) ||
                          (av[p] == av[p - 1] && dj[p] < dj[p - 1]);
                if (sw) {
                    float t = av[p]; av[p] = av[p - 1]; av[p - 1] = t;
                    int u = dj[p]; dj[p] = dj[p - 1]; dj[p - 1] = u;
                }
            }
        }

        float rs = 0.f;
#pragma unroll
        for (int q = 0; q < TK; q++) {
            rs += av[q];
            g_tv[i * TK + q] = av[q];
            g_ti[i * TK + q] = dj[q];
        }
        g_dinv[i] = rsqrtf(rs);
    }
}

// ---------------- 7) scatter sparse A into dense output (if requested) ----------------
__global__ void k_scatterA(float* __restrict__ A) {
    int e = blockIdx.x * blockDim.x + threadIdx.x;
    if (e < NN * TK) {
        int row = e / TK;
        A[(size_t)row * NN + g_ti[e]] = g_tv[e];
    }
}

// ---------------- 8) out = leaky(A_hat @ G) via 5-neighbor gather ----------------
__global__ void k_out(float* __restrict__ out) {
    int i = blockIdx.x;
    int c4 = threadIdx.x;   // 64 threads, one float4 column each
    float di = g_dinv[i];
    float4 acc = make_float4(0.f, 0.f, 0.f, 0.f);
#pragma unroll
    for (int q = 0; q < TK; q++) {
        int j = g_ti[i * TK + q];
        float w = di * g_tv[i * TK + q] * g_dinv[j];
        float4 g = ((const float4*)(g_G + (size_t)j * DD))[c4];
        acc.x += w * g.x; acc.y += w * g.y; acc.z += w * g.z; acc.w += w * g.w;
    }
    acc.x = acc.x >= 0.f ? acc.x : 0.01f * acc.x;
    acc.y = acc.y >= 0.f ? acc.y : 0.01f * acc.y;
    acc.z = acc.z >= 0.f ? acc.z : 0.01f * acc.z;
    acc.w = acc.w >= 0.f ? acc.w : 0.01f * acc.w;
    ((float4*)(out + (size_t)i * DD))[c4] = acc;
}

// ---------------- launcher ----------------
extern "C" void kernel_launch(void* const* d_in, const int* in_sizes, int n_in,
                              void* d_out, int out_size) {
    const float* H     = (const float*)d_in[0];
    const float* gamma = (const float*)d_in[1];
    const float* beta  = (const float*)d_in[2];
    const float* Wt    = (const float*)d_in[3];
    const float* bt    = (const float*)d_in[4];
    const float* Wo    = (const float*)d_in[5];
    const float* bo    = (const float*)d_in[6];

    float* outbuf = (float*)d_out;
    const long long OUT_ND = (long long)NN * DD;
    const long long A_NN   = (long long)NN * NN;

    float* outp = nullptr;
    float* Ap   = nullptr;
    long long osz = (long long)out_size;
    if (osz == OUT_ND + A_NN)      { outp = outbuf; Ap = outbuf + OUT_ND; }
    else if (osz == A_NN)          { Ap = outbuf; }
    else if (osz == OUT_ND)        { outp = outbuf; }
    else                           { outp = outbuf; if (osz >= OUT_ND + A_NN) Ap = outbuf + OUT_ND; }

    size_t main_smem = (size_t)(2 * 256 * 64 + 64 * 65) * sizeof(float);
    cudaFuncSetAttribute(k_main, cudaFuncAttributeMaxDynamicSharedMemorySize, (int)main_smem);

    k_stats1<<<32, 256>>>(H);
    k_stats2<<<1, 256>>>(gamma, beta);
    k_hnT<<<NN / 32, 256>>>(H);
    {
        dim3 g(NN / 64, 8);
        k_gemm<<<g, 256>>>(Wt, bt, Wo, bo);
    }
    k_norm<<<NN / 32, 256>>>();
    k_main<<<NN / 64, 256, main_smem>>>();

    if (Ap) {
        cudaMemsetAsync(Ap, 0, (size_t)A_NN * sizeof(float), 0);
        k_scatterA<<<(NN * TK + 255) / 256, 256>>>(Ap);
    }
    if (outp) {
        k_out<<<NN, 64>>>(outp);
    }
}